// round 16
// baseline (speedup 1.0000x reference)
#include <cuda_runtime.h>
#include <cuda_bf16.h>
#include <cstdint>
#include <math.h>

#define BATCH 4
#define SEQ   2048
#define DM    1024
#define NH    16
#define DK    64
#define MROWS (BATCH * SEQ)   // 8192

typedef __nv_bfloat16 bf16;

// ---------------- scratch (allocation-free: __device__ globals) ----------------
__device__ bf16 g_Xhi[MROWS * DM], g_Xlo[MROWS * DM];
__device__ bf16 g_Qh[MROWS * DM], g_Ql[MROWS * DM];
__device__ bf16 g_Kh[MROWS * DM], g_Kl[MROWS * DM];
__device__ bf16 g_Vh[MROWS * DM], g_Vl[MROWS * DM];
__device__ bf16 g_Ahi[MROWS * DM], g_Alo[MROWS * DM];

__device__ bf16 g_Wqh[DM * DM], g_Wql[DM * DM];
__device__ bf16 g_Wkh[DM * DM], g_Wkl[DM * DM];
__device__ bf16 g_Wvh[DM * DM], g_Wvl[DM * DM];
__device__ bf16 g_Woh[DM * DM], g_Wol[DM * DM];

// ---------------- common helpers ----------------
__device__ __forceinline__ uint32_t smem_u32(const void* p) {
    uint32_t a;
    asm("{ .reg .u64 t; cvta.to.shared.u64 t, %1; cvt.u32.u64 %0, t; }"
        : "=r"(a) : "l"(p));
    return a;
}
#define CP_ASYNC16(dst, src) \
    asm volatile("cp.async.cg.shared.global [%0], [%1], 16;" :: "r"(dst), "l"(src))
#define CP_COMMIT() asm volatile("cp.async.commit_group;" ::: "memory")
#define CP_WAIT(n)  asm volatile("cp.async.wait_group %0;" :: "n"(n) : "memory")

__device__ __forceinline__ void mma_bf16(float* d, const uint32_t* a,
                                         uint32_t b0, uint32_t b1) {
    asm volatile(
        "mma.sync.aligned.m16n8k16.row.col.f32.bf16.bf16.f32 "
        "{%0,%1,%2,%3}, {%4,%5,%6,%7}, {%8,%9}, {%0,%1,%2,%3};"
        : "+f"(d[0]), "+f"(d[1]), "+f"(d[2]), "+f"(d[3])
        : "r"(a[0]), "r"(a[1]), "r"(a[2]), "r"(a[3]), "r"(b0), "r"(b1));
}
__device__ __forceinline__ void ldsm_x4(uint32_t& r0, uint32_t& r1,
                                        uint32_t& r2, uint32_t& r3, uint32_t addr) {
    asm volatile("ldmatrix.sync.aligned.m8n8.x4.shared.b16 {%0,%1,%2,%3}, [%4];"
                 : "=r"(r0), "=r"(r1), "=r"(r2), "=r"(r3) : "r"(addr));
}
__device__ __forceinline__ void ldsm_x4_trans(uint32_t& r0, uint32_t& r1,
                                              uint32_t& r2, uint32_t& r3, uint32_t addr) {
    asm volatile("ldmatrix.sync.aligned.m8n8.x4.trans.shared.b16 {%0,%1,%2,%3}, [%4];"
                 : "=r"(r0), "=r"(r1), "=r"(r2), "=r"(r3) : "r"(addr));
}
__device__ __forceinline__ uint32_t pack_bf16x2(float lo, float hi) {
    uint32_t d;
    asm("cvt.rn.bf16x2.f32 %0, %1, %2;" : "=r"(d) : "f"(hi), "f"(lo));
    return d;
}
// pack pair to bf16x2 hi word + residual word (lo = x - bf16(x))
__device__ __forceinline__ void split_pack(float x0, float x1,
                                           uint32_t& ph, uint32_t& pl) {
    ph = pack_bf16x2(x0, x1);
    float f0 = __uint_as_float(ph << 16);
    float f1 = __uint_as_float(ph & 0xFFFF0000u);
    pl = pack_bf16x2(x0 - f0, x1 - f1);
}

// ---------------- conversion kernels ----------------
__global__ void convert_hilo(const float4* __restrict__ x,
                             uint2* __restrict__ hi, uint2* __restrict__ lo, int n4) {
    int i = blockIdx.x * 256 + threadIdx.x;
    if (i >= n4) return;
    float4 v = x[i];
    bf16 h0 = __float2bfloat16(v.x), h1 = __float2bfloat16(v.y);
    bf16 h2 = __float2bfloat16(v.z), h3 = __float2bfloat16(v.w);
    bf16 l0 = __float2bfloat16(v.x - __bfloat162float(h0));
    bf16 l1 = __float2bfloat16(v.y - __bfloat162float(h1));
    bf16 l2 = __float2bfloat16(v.z - __bfloat162float(h2));
    bf16 l3 = __float2bfloat16(v.w - __bfloat162float(h3));
    union U { bf16 b[4]; uint2 u; } uh, ul;
    uh.b[0] = h0; uh.b[1] = h1; uh.b[2] = h2; uh.b[3] = h3;
    ul.b[0] = l0; ul.b[1] = l1; ul.b[2] = l2; ul.b[3] = l3;
    hi[i] = uh.u;
    lo[i] = ul.u;
}

__global__ void wtrans_all(const float* __restrict__ W0, const float* __restrict__ W1,
                           const float* __restrict__ W2, const float* __restrict__ W3) {
    __shared__ float t[32][33];
    const float* W;
    bf16 *Th, *Tl;
    switch (blockIdx.z) {
        case 0:  W = W0; Th = g_Wqh; Tl = g_Wql; break;
        case 1:  W = W1; Th = g_Wkh; Tl = g_Wkl; break;
        case 2:  W = W2; Th = g_Wvh; Tl = g_Wvl; break;
        default: W = W3; Th = g_Woh; Tl = g_Wol; break;
    }
    int tx = threadIdx.x, ty = threadIdx.y;
    int col  = blockIdx.x * 32 + tx;
    int row0 = blockIdx.y * 32;
    for (int j = ty; j < 32; j += 8)
        t[j][tx] = W[(size_t)(row0 + j) * DM + col];
    __syncthreads();
    int ocol  = row0 + tx;
    int orow0 = blockIdx.x * 32;
    for (int j = ty; j < 32; j += 8) {
        float v = t[tx][j];
        bf16 h = __float2bfloat16(v);
        bf16 l = __float2bfloat16(v - __bfloat162float(h));
        Th[(size_t)(orow0 + j) * DM + ocol] = h;
        Tl[(size_t)(orow0 + j) * DM + ocol] = l;
    }
}

// ---------------- HMMA bf16x3 GEMM core: 4 warps, 64x64 warp tiles ----------------
#define GBK 32
#define MAT_ELEMS (128 * GBK)
#define STAGE_ELEMS (4 * MAT_ELEMS)
#define GEMM_SMEM_BYTES (2 * STAGE_ELEMS * 2)   // 64 KB

__device__ __forceinline__ int swz(int row, int k) {
    int quad = (k >> 3) ^ (row & 3) ^ ((row >> 2) & 1);
    return row * GBK + quad * 8 + (k & 7);
}

template<bool SPLIT>
__device__ __forceinline__
void gemm_core(const bf16* __restrict__ Ahi, const bf16* __restrict__ Alo,
               const bf16* __restrict__ Bhi, const bf16* __restrict__ Blo,
               float* __restrict__ C, bf16* __restrict__ Ch, bf16* __restrict__ Cl,
               int N, int K, bf16* sm) {
    const int tid = threadIdx.x;
    const int wid = tid >> 5;        // 0..3
    const int lane = tid & 31;
    const int rowC = blockIdx.y * 128;
    const int colC = blockIdx.x * 128;

    const int wm = (wid & 1) * 64;
    const int wn = (wid >> 1) * 64;
    const int r  = lane >> 2;
    const int cq = (lane & 3) * 2;

    float acc[4][8][4];
#pragma unroll
    for (int i = 0; i < 4; i++)
#pragma unroll
        for (int j = 0; j < 8; j++)
#pragma unroll
            for (int t = 0; t < 4; t++) acc[i][j][t] = 0.f;

    auto load_stage = [&](int s, int c) {
        const size_t k0 = (size_t)c * GBK;
        bf16* st = sm + s * STAGE_ELEMS;
#pragma unroll
        for (int t = 0; t < 4; t++) {
            int idx = tid + t * 128;        // 0..511
            int row = idx >> 2;
            int q   = idx & 3;
            uint32_t dsto = smem_u32(st) + swz(row, q * 8) * 2;
            const bf16* ga = Ahi + (size_t)(rowC + row) * K + k0 + q * 8;
            const bf16* gl = Alo + (size_t)(rowC + row) * K + k0 + q * 8;
            const bf16* gb = Bhi + (size_t)(colC + row) * K + k0 + q * 8;
            const bf16* gc = Blo + (size_t)(colC + row) * K + k0 + q * 8;
            CP_ASYNC16(dsto,                 ga);
            CP_ASYNC16(dsto + MAT_ELEMS * 2, gl);
            CP_ASYNC16(dsto + MAT_ELEMS * 4, gb);
            CP_ASYNC16(dsto + MAT_ELEMS * 6, gc);
        }
    };

    const int nchunk = K / GBK;
    load_stage(0, 0);
    CP_COMMIT();

    const int a_r  = lane & 15;
    const int a_k  = (lane >> 4) * 8;
    const int b_j  = (lane >> 4) & 1;
    const int b_h  = (lane >> 3) & 1;
    const int b_r  = lane & 7;

    for (int c = 0; c < nchunk; c++) {
        const int s = c & 1;
        if (c + 1 < nchunk) {
            load_stage(s ^ 1, c + 1);
            CP_COMMIT();
            CP_WAIT(1);
        } else {
            CP_WAIT(0);
        }
        __syncthreads();

        const bf16* Ah_s = sm + s * STAGE_ELEMS;
        const bf16* Al_s = Ah_s + MAT_ELEMS;
        const bf16* Bh_s = Ah_s + 2 * MAT_ELEMS;
        const bf16* Bl_s = Ah_s + 3 * MAT_ELEMS;

#pragma unroll
        for (int kk = 0; kk < GBK; kk += 16) {
            uint32_t ah[4][4], bb[8][2];
#pragma unroll
            for (int i = 0; i < 4; i++)
                ldsm_x4(ah[i][0], ah[i][1], ah[i][2], ah[i][3],
                        smem_u32(Ah_s + swz(wm + i * 16 + a_r, kk + a_k)));
#pragma unroll
            for (int jp = 0; jp < 4; jp++)
                ldsm_x4(bb[jp*2][0], bb[jp*2][1], bb[jp*2+1][0], bb[jp*2+1][1],
                        smem_u32(Bh_s + swz(wn + (jp*2 + b_j) * 8 + b_r, kk + b_h * 8)));
#pragma unroll
            for (int i = 0; i < 4; i++)
#pragma unroll
                for (int j = 0; j < 8; j++)
                    mma_bf16(acc[i][j], ah[i], bb[j][0], bb[j][1]);
            uint32_t bl[8][2];
#pragma unroll
            for (int jp = 0; jp < 4; jp++)
                ldsm_x4(bl[jp*2][0], bl[jp*2][1], bl[jp*2+1][0], bl[jp*2+1][1],
                        smem_u32(Bl_s + swz(wn + (jp*2 + b_j) * 8 + b_r, kk + b_h * 8)));
#pragma unroll
            for (int i = 0; i < 4; i++)
#pragma unroll
                for (int j = 0; j < 8; j++)
                    mma_bf16(acc[i][j], ah[i], bl[j][0], bl[j][1]);
            uint32_t al[4][4];
#pragma unroll
            for (int i = 0; i < 4; i++)
                ldsm_x4(al[i][0], al[i][1], al[i][2], al[i][3],
                        smem_u32(Al_s + swz(wm + i * 16 + a_r, kk + a_k)));
#pragma unroll
            for (int i = 0; i < 4; i++)
#pragma unroll
                for (int j = 0; j < 8; j++)
                    mma_bf16(acc[i][j], al[i], bb[j][0], bb[j][1]);
        }
        __syncthreads();
    }

#pragma unroll
    for (int i = 0; i < 4; i++) {
        int row0 = rowC + wm + i * 16 + r;
#pragma unroll
        for (int j = 0; j < 8; j++) {
            int col = colC + wn + j * 8 + cq;
            if (SPLIT) {
#pragma unroll
                for (int p = 0; p < 2; p++) {
                    uint32_t ph, pl;
                    split_pack(acc[i][j][p * 2 + 0], acc[i][j][p * 2 + 1], ph, pl);
                    size_t off = (size_t)(row0 + p * 8) * N + col;
                    *(uint32_t*)(Ch + off) = ph;
                    *(uint32_t*)(Cl + off) = pl;
                }
            } else {
                *(float2*)(C + (size_t)row0 * N + col) =
                    make_float2(acc[i][j][0], acc[i][j][1]);
                *(float2*)(C + (size_t)(row0 + 8) * N + col) =
                    make_float2(acc[i][j][2], acc[i][j][3]);
            }
        }
    }
}

__global__ __launch_bounds__(128, 2)
void gemm_qkv() {
    extern __shared__ bf16 sm[];
    if (blockIdx.z == 0)
        gemm_core<true>(g_Xhi, g_Xlo, g_Wqh, g_Wql, nullptr, g_Qh, g_Ql, DM, DM, sm);
    else if (blockIdx.z == 1)
        gemm_core<true>(g_Xhi, g_Xlo, g_Wkh, g_Wkl, nullptr, g_Kh, g_Kl, DM, DM, sm);
    else
        gemm_core<true>(g_Xhi, g_Xlo, g_Wvh, g_Wvl, nullptr, g_Vh, g_Vl, DM, DM, sm);
}

__global__ __launch_bounds__(128, 2)
void gemm_out(float* __restrict__ C) {
    extern __shared__ bf16 sm[];
    gemm_core<false>(g_Ahi, g_Alo, g_Woh, g_Wol, C, nullptr, nullptr, DM, DM, sm);
}

// ---------------- HMMA flash attention: full K+V double-buffer via dead-Q reuse ----------------
// smem layout (elems):
//   [0,2A)   : Q hi/lo at t=0; after Q fragments are in registers, reused as V stage 1
//   [2A,4A)  : K stage 0 (hi,lo)
//   [4A,6A)  : K stage 1 (hi,lo)
//   [6A,8A)  : V stage 0 (hi,lo)
#define AST  72
#define AMAT (64 * AST)
#define ATT_SMEM_BYTES (8 * AMAT * 2)      // 73728 B
#define EXPC 0.18033688f                   // 0.125 * log2(e)

__global__ __launch_bounds__(128, 3)
void attn_hmma() {
    extern __shared__ bf16 sm[];
    const int bh = blockIdx.y;
    const int b  = bh >> 4;
    const int h  = bh & 15;
    const int m0 = ((int)gridDim.x - 1 - (int)blockIdx.x) * 64;

    const int tid  = threadIdx.x;
    const int wid  = tid >> 5;
    const int lane = tid & 31;
    const int r    = lane >> 2;
    const int cq   = (lane & 3) * 2;
    const int wm   = wid * 16;

    const size_t rowbase = (size_t)b * SEQ;
    const int    colb    = h * DK;

    const uint32_t smb = smem_u32(sm);

    // K stage s base; V stage 0 at 6A, V stage 1 overlaps Q region (0)
    auto kstage = [&](int s) { return smb + (uint32_t)(2 + s * 2) * AMAT * 2; };
    auto vstage = [&](int s) { return s == 0 ? smb + 6 * AMAT * 2 : smb; };

    // ---- prologue: Q + KV(0) ----
    for (int i = tid; i < 512; i += 128) {
        int row = i >> 3, q = i & 7;
        uint32_t dst = smb + (uint32_t)(row * AST + q * 8) * 2;
        size_t g = (rowbase + m0 + row) * (size_t)DM + colb + q * 8;
        CP_ASYNC16(dst,            g_Qh + g);
        CP_ASYNC16(dst + AMAT * 2, g_Ql + g);
    }
    CP_COMMIT();

    auto load_kv = [&](int s, int n0) {
        const uint32_t kb = kstage(s);
        const uint32_t vb = vstage(s);
        for (int i = tid; i < 512; i += 128) {
            int row = i >> 3, q = i & 7;
            uint32_t off = (uint32_t)(row * AST + q * 8) * 2;
            size_t g = (rowbase + n0 + row) * (size_t)DM + colb + q * 8;
            CP_ASYNC16(kb + off,            g_Kh + g);
            CP_ASYNC16(kb + AMAT * 2 + off, g_Kl + g);
            CP_ASYNC16(vb + off,            g_Vh + g);
            CP_ASYNC16(vb + AMAT * 2 + off, g_Vl + g);
        }
    };

    load_kv(0, 0);
    CP_COMMIT();
    CP_WAIT(0);
    __syncthreads();                 // Q + K0 + V0 resident

    const int a_r = lane & 15;
    const int a_k = (lane >> 4) * 8;
    const int b_j = (lane >> 4) & 1;
    const int b_h = (lane >> 3) & 1;
    const int b_r = lane & 7;

    // Q fragments resident (hi + lo)
    uint32_t qh[4][4], ql[4][4];
#pragma unroll
    for (int kc = 0; kc < 4; kc++) {
        uint32_t ad = smb + (uint32_t)((wm + a_r) * AST + kc * 16 + a_k) * 2;
        ldsm_x4(qh[kc][0], qh[kc][1], qh[kc][2], qh[kc][3], ad);
        ldsm_x4(ql[kc][0], ql[kc][1], ql[kc][2], ql[kc][3], ad + AMAT * 2);
    }
    __syncthreads();                 // all warps done reading Q smem (V1 may now overwrite)

    const int T = m0 / 64 + 1;
    float l_i[2] = {0.f, 0.f};
    float O[8][4];
#pragma unroll
    for (int j = 0; j < 8; j++)
#pragma unroll
        for (int t = 0; t < 4; t++) O[j][t] = 0.f;

    for (int t = 0; t < T; t++) {
        const int s = t & 1;
        // issue loads for t+1 into the other stage (covered by this tile's compute)
        if (t + 1 < T) {
            load_kv(s ^ 1, (t + 1) * 64);
            CP_COMMIT();
        }

        const uint32_t kbase = kstage(s);
        const uint32_t vbase = vstage(s);

        // ---- QK^T on K(t) ----
        float sacc[8][4];
#pragma unroll
        for (int j = 0; j < 8; j++)
#pragma unroll
            for (int c = 0; c < 4; c++) sacc[j][c] = 0.f;

#pragma unroll
        for (int kc = 0; kc < 4; kc++) {
#pragma unroll
            for (int jp = 0; jp < 4; jp++) {
                uint32_t ad = kbase
                    + (uint32_t)(((jp * 2 + b_j) * 8 + b_r) * AST + kc * 16 + b_h * 8) * 2;
                uint32_t kh0, kh1, kh2, kh3, kl0, kl1, kl2, kl3;
                ldsm_x4(kh0, kh1, kh2, kh3, ad);
                ldsm_x4(kl0, kl1, kl2, kl3, ad + AMAT * 2);
                mma_bf16(sacc[jp*2],   qh[kc], kh0, kh1);
                mma_bf16(sacc[jp*2],   qh[kc], kl0, kl1);
                mma_bf16(sacc[jp*2],   ql[kc], kh0, kh1);
                mma_bf16(sacc[jp*2+1], qh[kc], kh2, kh3);
                mma_bf16(sacc[jp*2+1], qh[kc], kl2, kl3);
                mma_bf16(sacc[jp*2+1], ql[kc], kh2, kh3);
            }
        }

        // causal mask on diagonal tile
        if (t == T - 1) {
            const int qr0 = m0 + wm + r;
#pragma unroll
            for (int j = 0; j < 8; j++) {
                const int key0 = t * 64 + j * 8 + cq;
                if (key0 + 0 > qr0)     sacc[j][0] = -INFINITY;
                if (key0 + 1 > qr0)     sacc[j][1] = -INFINITY;
                if (key0 + 0 > qr0 + 8) sacc[j][2] = -INFINITY;
                if (key0 + 1 > qr0 + 8) sacc[j][3] = -INFINITY;
            }
        }

        // no-max softmax: p = 2^(s * EXPC)
#pragma unroll
        for (int j = 0; j < 8; j++) {
            sacc[j][0] = exp2f(sacc[j][0] * EXPC); l_i[0] += sacc[j][0];
            sacc[j][1] = exp2f(sacc[j][1] * EXPC); l_i[0] += sacc[j][1];
            sacc[j][2] = exp2f(sacc[j][2] * EXPC); l_i[1] += sacc[j][2];
            sacc[j][3] = exp2f(sacc[j][3] * EXPC); l_i[1] += sacc[j][3];
        }

        // ---- PV on V(t) ----
#pragma unroll
        for (int kc = 0; kc < 4; kc++) {
            uint32_t ph[4], pl[4];
#pragma unroll
            for (int half = 0; half < 2; half++) {
                const int jj = kc * 2 + half;
                split_pack(sacc[jj][0], sacc[jj][1], ph[half * 2 + 0], pl[half * 2 + 0]);
                split_pack(sacc[jj][2], sacc[jj][3], ph[half * 2 + 1], pl[half * 2 + 1]);
            }
            const int lrow = kc * 16 + (lane & 7) + ((lane >> 3) & 1) * 8;
            const int lcolh = (lane >> 4);
#pragma unroll
            for (int jp = 0; jp < 4; jp++) {
                uint32_t addr = vbase
                    + (uint32_t)(lrow * AST + (jp * 2 + lcolh) * 8) * 2;
                uint32_t vh0, vh1, vh2, vh3, vl0, vl1, vl2, vl3;
                ldsm_x4_trans(vh0, vh1, vh2, vh3, addr);
                ldsm_x4_trans(vl0, vl1, vl2, vl3, addr + AMAT * 2);
                mma_bf16(O[jp * 2],     ph, vh0, vh1);
                mma_bf16(O[jp * 2],     ph, vl0, vl1);
                mma_bf16(O[jp * 2],     pl, vh0, vh1);
                mma_bf16(O[jp * 2 + 1], ph, vh2, vh3);
                mma_bf16(O[jp * 2 + 1], ph, vl2, vl3);
                mma_bf16(O[jp * 2 + 1], pl, vh2, vh3);
            }
        }

        // drain t+1's loads + release stage s for t+2's loads
        if (t + 1 < T) {
            CP_WAIT(0);
            __syncthreads();
        }
    }

    // final l reduction across the quad
    l_i[0] += __shfl_xor_sync(0xffffffffu, l_i[0], 1);
    l_i[0] += __shfl_xor_sync(0xffffffffu, l_i[0], 2);
    l_i[1] += __shfl_xor_sync(0xffffffffu, l_i[1], 1);
    l_i[1] += __shfl_xor_sync(0xffffffffu, l_i[1], 2);
    const float inv0 = 1.f / l_i[0];
    const float inv1 = 1.f / l_i[1];
#pragma unroll
    for (int j = 0; j < 8; j++) {
        const int col = colb + j * 8 + cq;
        const size_t row0 = (rowbase + m0 + wm + r) * (size_t)DM + col;
        const size_t row8 = row0 + 8 * (size_t)DM;
        uint32_t ph0, pl0, ph1, pl1;
        split_pack(O[j][0] * inv0, O[j][1] * inv0, ph0, pl0);
        split_pack(O[j][2] * inv1, O[j][3] * inv1, ph1, pl1);
        *(uint32_t*)(g_Ahi + row0) = ph0;
        *(uint32_t*)(g_Ahi + row8) = ph1;
        *(uint32_t*)(g_Alo + row0) = pl0;
        *(uint32_t*)(g_Alo + row8) = pl1;
    }
}

// ================= launch =================
extern "C" void kernel_launch(void* const* d_in, const int* in_sizes, int n_in,
                              void* d_out, int out_size) {
    (void)in_sizes; (void)n_in; (void)out_size;
    const float* X  = (const float*)d_in[0];
    const float* Wq = (const float*)d_in[1];
    const float* Wk = (const float*)d_in[2];
    const float* Wv = (const float*)d_in[3];
    const float* Wo = (const float*)d_in[4];

    bf16 *xhi, *xlo;
    cudaGetSymbolAddress((void**)&xhi, g_Xhi);
    cudaGetSymbolAddress((void**)&xlo, g_Xlo);

    cudaFuncSetAttribute(gemm_qkv,
                         cudaFuncAttributeMaxDynamicSharedMemorySize, GEMM_SMEM_BYTES);
    cudaFuncSetAttribute(gemm_out,
                         cudaFuncAttributeMaxDynamicSharedMemorySize, GEMM_SMEM_BYTES);
    cudaFuncSetAttribute(attn_hmma,
                         cudaFuncAttributeMaxDynamicSharedMemorySize, ATT_SMEM_BYTES);

    {
        int n4 = MROWS * DM / 4;
        convert_hilo<<<(n4 + 255) / 256, 256>>>((const float4*)X, (uint2*)xhi, (uint2*)xlo, n4);
    }
    wtrans_all<<<dim3(DM / 32, DM / 32, 4), dim3(32, 8)>>>(Wq, Wk, Wv, Wo);

    gemm_qkv<<<dim3(DM / 128, MROWS / 128, 3), 128, GEMM_SMEM_BYTES>>>();

    attn_hmma<<<dim3(SEQ / 64, BATCH * NH), 128, ATT_SMEM_BYTES>>>();

    gemm_out<<<dim3(DM / 128, MROWS / 128), 128, GEMM_SMEM_BYTES>>>((float*)d_out);
}

// round 17
// speedup vs baseline: 1.0307x; 1.0307x over previous
#include <cuda_runtime.h>
#include <cuda_bf16.h>
#include <cstdint>
#include <math.h>

#define BATCH 4
#define SEQ   2048
#define DM    1024
#define NH    16
#define DK    64
#define MROWS (BATCH * SEQ)   // 8192

typedef __nv_bfloat16 bf16;

// ---------------- scratch (allocation-free: __device__ globals) ----------------
__device__ bf16 g_Xhi[MROWS * DM], g_Xlo[MROWS * DM];
__device__ bf16 g_Qh[MROWS * DM], g_Ql[MROWS * DM];
__device__ bf16 g_Kh[MROWS * DM], g_Kl[MROWS * DM];
__device__ bf16 g_Vh[MROWS * DM], g_Vl[MROWS * DM];
__device__ bf16 g_Ahi[MROWS * DM], g_Alo[MROWS * DM];

__device__ bf16 g_Wqh[DM * DM], g_Wql[DM * DM];
__device__ bf16 g_Wkh[DM * DM], g_Wkl[DM * DM];
__device__ bf16 g_Wvh[DM * DM], g_Wvl[DM * DM];
__device__ bf16 g_Woh[DM * DM], g_Wol[DM * DM];

// ---------------- common helpers ----------------
__device__ __forceinline__ uint32_t smem_u32(const void* p) {
    uint32_t a;
    asm("{ .reg .u64 t; cvta.to.shared.u64 t, %1; cvt.u32.u64 %0, t; }"
        : "=r"(a) : "l"(p));
    return a;
}
#define CP_ASYNC16(dst, src) \
    asm volatile("cp.async.cg.shared.global [%0], [%1], 16;" :: "r"(dst), "l"(src))
#define CP_COMMIT() asm volatile("cp.async.commit_group;" ::: "memory")
#define CP_WAIT(n)  asm volatile("cp.async.wait_group %0;" :: "n"(n) : "memory")

__device__ __forceinline__ void mma_bf16(float* d, const uint32_t* a,
                                         uint32_t b0, uint32_t b1) {
    asm volatile(
        "mma.sync.aligned.m16n8k16.row.col.f32.bf16.bf16.f32 "
        "{%0,%1,%2,%3}, {%4,%5,%6,%7}, {%8,%9}, {%0,%1,%2,%3};"
        : "+f"(d[0]), "+f"(d[1]), "+f"(d[2]), "+f"(d[3])
        : "r"(a[0]), "r"(a[1]), "r"(a[2]), "r"(a[3]), "r"(b0), "r"(b1));
}
__device__ __forceinline__ void ldsm_x4(uint32_t& r0, uint32_t& r1,
                                        uint32_t& r2, uint32_t& r3, uint32_t addr) {
    asm volatile("ldmatrix.sync.aligned.m8n8.x4.shared.b16 {%0,%1,%2,%3}, [%4];"
                 : "=r"(r0), "=r"(r1), "=r"(r2), "=r"(r3) : "r"(addr));
}
__device__ __forceinline__ void ldsm_x4_trans(uint32_t& r0, uint32_t& r1,
                                              uint32_t& r2, uint32_t& r3, uint32_t addr) {
    asm volatile("ldmatrix.sync.aligned.m8n8.x4.trans.shared.b16 {%0,%1,%2,%3}, [%4];"
                 : "=r"(r0), "=r"(r1), "=r"(r2), "=r"(r3) : "r"(addr));
}
__device__ __forceinline__ uint32_t pack_bf16x2(float lo, float hi) {
    uint32_t d;
    asm("cvt.rn.bf16x2.f32 %0, %1, %2;" : "=r"(d) : "f"(hi), "f"(lo));
    return d;
}
// pack pair to bf16x2 hi word + residual word (lo = x - bf16(x))
__device__ __forceinline__ void split_pack(float x0, float x1,
                                           uint32_t& ph, uint32_t& pl) {
    ph = pack_bf16x2(x0, x1);
    float f0 = __uint_as_float(ph << 16);
    float f1 = __uint_as_float(ph & 0xFFFF0000u);
    pl = pack_bf16x2(x0 - f0, x1 - f1);
}

// ---------------- conversion kernels ----------------
__global__ void convert_hilo(const float4* __restrict__ x,
                             uint2* __restrict__ hi, uint2* __restrict__ lo, int n4) {
    int i = blockIdx.x * 256 + threadIdx.x;
    if (i >= n4) return;
    float4 v = x[i];
    bf16 h0 = __float2bfloat16(v.x), h1 = __float2bfloat16(v.y);
    bf16 h2 = __float2bfloat16(v.z), h3 = __float2bfloat16(v.w);
    bf16 l0 = __float2bfloat16(v.x - __bfloat162float(h0));
    bf16 l1 = __float2bfloat16(v.y - __bfloat162float(h1));
    bf16 l2 = __float2bfloat16(v.z - __bfloat162float(h2));
    bf16 l3 = __float2bfloat16(v.w - __bfloat162float(h3));
    union U { bf16 b[4]; uint2 u; } uh, ul;
    uh.b[0] = h0; uh.b[1] = h1; uh.b[2] = h2; uh.b[3] = h3;
    ul.b[0] = l0; ul.b[1] = l1; ul.b[2] = l2; ul.b[3] = l3;
    hi[i] = uh.u;
    lo[i] = ul.u;
}

__global__ void wtrans_all(const float* __restrict__ W0, const float* __restrict__ W1,
                           const float* __restrict__ W2, const float* __restrict__ W3) {
    __shared__ float t[32][33];
    const float* W;
    bf16 *Th, *Tl;
    switch (blockIdx.z) {
        case 0:  W = W0; Th = g_Wqh; Tl = g_Wql; break;
        case 1:  W = W1; Th = g_Wkh; Tl = g_Wkl; break;
        case 2:  W = W2; Th = g_Wvh; Tl = g_Wvl; break;
        default: W = W3; Th = g_Woh; Tl = g_Wol; break;
    }
    int tx = threadIdx.x, ty = threadIdx.y;
    int col  = blockIdx.x * 32 + tx;
    int row0 = blockIdx.y * 32;
    for (int j = ty; j < 32; j += 8)
        t[j][tx] = W[(size_t)(row0 + j) * DM + col];
    __syncthreads();
    int ocol  = row0 + tx;
    int orow0 = blockIdx.x * 32;
    for (int j = ty; j < 32; j += 8) {
        float v = t[tx][j];
        bf16 h = __float2bfloat16(v);
        bf16 l = __float2bfloat16(v - __bfloat162float(h));
        Th[(size_t)(orow0 + j) * DM + ocol] = h;
        Tl[(size_t)(orow0 + j) * DM + ocol] = l;
    }
}

// ---------------- HMMA bf16x3 GEMM: 4 warps, 64x64 warp tiles, 3-stage pipeline ----------------
#define GBK 32
#define MAT_ELEMS (128 * GBK)
#define STAGE_ELEMS (4 * MAT_ELEMS)
#define GEMM_SMEM_BYTES (3 * STAGE_ELEMS * 2)   // 96 KB

__device__ __forceinline__ int swz(int row, int k) {
    int quad = (k >> 3) ^ (row & 3) ^ ((row >> 2) & 1);
    return row * GBK + quad * 8 + (k & 7);
}

template<bool SPLIT>
__device__ __forceinline__
void gemm_core(const bf16* __restrict__ Ahi, const bf16* __restrict__ Alo,
               const bf16* __restrict__ Bhi, const bf16* __restrict__ Blo,
               float* __restrict__ C, bf16* __restrict__ Ch, bf16* __restrict__ Cl,
               int N, int K, bf16* sm) {
    const int tid = threadIdx.x;
    const int wid = tid >> 5;        // 0..3
    const int lane = tid & 31;
    const int rowC = blockIdx.y * 128;
    const int colC = blockIdx.x * 128;

    const int wm = (wid & 1) * 64;
    const int wn = (wid >> 1) * 64;
    const int r  = lane >> 2;
    const int cq = (lane & 3) * 2;

    float acc[4][8][4];
#pragma unroll
    for (int i = 0; i < 4; i++)
#pragma unroll
        for (int j = 0; j < 8; j++)
#pragma unroll
            for (int t = 0; t < 4; t++) acc[i][j][t] = 0.f;

    auto load_stage = [&](int s, int c) {
        const size_t k0 = (size_t)c * GBK;
        bf16* st = sm + s * STAGE_ELEMS;
#pragma unroll
        for (int t = 0; t < 4; t++) {
            int idx = tid + t * 128;        // 0..511
            int row = idx >> 2;
            int q   = idx & 3;
            uint32_t dsto = smem_u32(st) + swz(row, q * 8) * 2;
            const bf16* ga = Ahi + (size_t)(rowC + row) * K + k0 + q * 8;
            const bf16* gl = Alo + (size_t)(rowC + row) * K + k0 + q * 8;
            const bf16* gb = Bhi + (size_t)(colC + row) * K + k0 + q * 8;
            const bf16* gc = Blo + (size_t)(colC + row) * K + k0 + q * 8;
            CP_ASYNC16(dsto,                 ga);
            CP_ASYNC16(dsto + MAT_ELEMS * 2, gl);
            CP_ASYNC16(dsto + MAT_ELEMS * 4, gb);
            CP_ASYNC16(dsto + MAT_ELEMS * 6, gc);
        }
    };

    const int nchunk = K / GBK;
    load_stage(0, 0); CP_COMMIT();
    load_stage(1, 1); CP_COMMIT();

    const int a_r  = lane & 15;
    const int a_k  = (lane >> 4) * 8;
    const int b_j  = (lane >> 4) & 1;
    const int b_h  = (lane >> 3) & 1;
    const int b_r  = lane & 7;

    int s = 0;                        // stage = c % 3
    for (int c = 0; c < nchunk; c++) {
        // chunk c must be complete: it's the oldest pending group.
        if (c < nchunk - 1) CP_WAIT(1); else CP_WAIT(0);
        __syncthreads();              // also releases the stage written 2 chunks ahead
        if (c + 2 < nchunk) {
            int s2 = s + 2; if (s2 >= 3) s2 -= 3;
            load_stage(s2, c + 2);
            CP_COMMIT();
        }

        const bf16* Ah_s = sm + s * STAGE_ELEMS;
        const bf16* Al_s = Ah_s + MAT_ELEMS;
        const bf16* Bh_s = Ah_s + 2 * MAT_ELEMS;
        const bf16* Bl_s = Ah_s + 3 * MAT_ELEMS;

#pragma unroll
        for (int kk = 0; kk < GBK; kk += 16) {
            uint32_t ah[4][4], bb[8][2];
#pragma unroll
            for (int i = 0; i < 4; i++)
                ldsm_x4(ah[i][0], ah[i][1], ah[i][2], ah[i][3],
                        smem_u32(Ah_s + swz(wm + i * 16 + a_r, kk + a_k)));
#pragma unroll
            for (int jp = 0; jp < 4; jp++)
                ldsm_x4(bb[jp*2][0], bb[jp*2][1], bb[jp*2+1][0], bb[jp*2+1][1],
                        smem_u32(Bh_s + swz(wn + (jp*2 + b_j) * 8 + b_r, kk + b_h * 8)));
#pragma unroll
            for (int i = 0; i < 4; i++)
#pragma unroll
                for (int j = 0; j < 8; j++)
                    mma_bf16(acc[i][j], ah[i], bb[j][0], bb[j][1]);
            uint32_t bl[8][2];
#pragma unroll
            for (int jp = 0; jp < 4; jp++)
                ldsm_x4(bl[jp*2][0], bl[jp*2][1], bl[jp*2+1][0], bl[jp*2+1][1],
                        smem_u32(Bl_s + swz(wn + (jp*2 + b_j) * 8 + b_r, kk + b_h * 8)));
#pragma unroll
            for (int i = 0; i < 4; i++)
#pragma unroll
                for (int j = 0; j < 8; j++)
                    mma_bf16(acc[i][j], ah[i], bl[j][0], bl[j][1]);
            uint32_t al[4][4];
#pragma unroll
            for (int i = 0; i < 4; i++)
                ldsm_x4(al[i][0], al[i][1], al[i][2], al[i][3],
                        smem_u32(Al_s + swz(wm + i * 16 + a_r, kk + a_k)));
#pragma unroll
            for (int i = 0; i < 4; i++)
#pragma unroll
                for (int j = 0; j < 8; j++)
                    mma_bf16(acc[i][j], al[i], bb[j][0], bb[j][1]);
        }
        if (++s >= 3) s -= 3;
    }

#pragma unroll
    for (int i = 0; i < 4; i++) {
        int row0 = rowC + wm + i * 16 + r;
#pragma unroll
        for (int j = 0; j < 8; j++) {
            int col = colC + wn + j * 8 + cq;
            if (SPLIT) {
#pragma unroll
                for (int p = 0; p < 2; p++) {
                    uint32_t ph, pl;
                    split_pack(acc[i][j][p * 2 + 0], acc[i][j][p * 2 + 1], ph, pl);
                    size_t off = (size_t)(row0 + p * 8) * N + col;
                    *(uint32_t*)(Ch + off) = ph;
                    *(uint32_t*)(Cl + off) = pl;
                }
            } else {
                *(float2*)(C + (size_t)row0 * N + col) =
                    make_float2(acc[i][j][0], acc[i][j][1]);
                *(float2*)(C + (size_t)(row0 + 8) * N + col) =
                    make_float2(acc[i][j][2], acc[i][j][3]);
            }
        }
    }
}

__global__ __launch_bounds__(128, 2)
void gemm_qkv() {
    extern __shared__ bf16 sm[];
    if (blockIdx.z == 0)
        gemm_core<true>(g_Xhi, g_Xlo, g_Wqh, g_Wql, nullptr, g_Qh, g_Ql, DM, DM, sm);
    else if (blockIdx.z == 1)
        gemm_core<true>(g_Xhi, g_Xlo, g_Wkh, g_Wkl, nullptr, g_Kh, g_Kl, DM, DM, sm);
    else
        gemm_core<true>(g_Xhi, g_Xlo, g_Wvh, g_Wvl, nullptr, g_Vh, g_Vl, DM, DM, sm);
}

__global__ __launch_bounds__(128, 2)
void gemm_out(float* __restrict__ C) {
    extern __shared__ bf16 sm[];
    gemm_core<false>(g_Ahi, g_Alo, g_Woh, g_Wol, C, nullptr, nullptr, DM, DM, sm);
}

// ---------------- HMMA flash attention (R15 exact: no-max softmax, K dbl-buf, split waits) ----------------
#define AST  72
#define AMAT (64 * AST)
// smem layout (elems): Q hi/lo [0,2A) | Kstage0 [2A,4A) | Kstage1 [4A,6A) | V hi/lo [6A,8A)
#define ATT_SMEM_BYTES (8 * AMAT * 2)      // 73728 B
#define EXPC 0.18033688f                   // 0.125 * log2(e)

__global__ __launch_bounds__(128, 3)
void attn_hmma() {
    extern __shared__ bf16 sm[];
    const int bh = blockIdx.y;
    const int b  = bh >> 4;
    const int h  = bh & 15;
    const int m0 = ((int)gridDim.x - 1 - (int)blockIdx.x) * 64;

    const int tid  = threadIdx.x;
    const int wid  = tid >> 5;
    const int lane = tid & 31;
    const int r    = lane >> 2;
    const int cq   = (lane & 3) * 2;
    const int wm   = wid * 16;

    const size_t rowbase = (size_t)b * SEQ;
    const int    colb    = h * DK;

    const uint32_t smb   = smem_u32(sm);
    const uint32_t vbase = smb + 6 * AMAT * 2;

    // Q tile load (hi/lo) — group 1
    for (int i = tid; i < 512; i += 128) {
        int row = i >> 3, q = i & 7;
        uint32_t dst = smb + (uint32_t)(row * AST + q * 8) * 2;
        size_t g = (rowbase + m0 + row) * (size_t)DM + colb + q * 8;
        CP_ASYNC16(dst,            g_Qh + g);
        CP_ASYNC16(dst + AMAT * 2, g_Ql + g);
    }
    CP_COMMIT();

    auto load_k = [&](int s, int n0) {
        uint32_t kb = smb + (uint32_t)(2 + s * 2) * AMAT * 2;
        for (int i = tid; i < 512; i += 128) {
            int row = i >> 3, q = i & 7;
            uint32_t off = (uint32_t)(row * AST + q * 8) * 2;
            size_t g = (rowbase + n0 + row) * (size_t)DM + colb + q * 8;
            CP_ASYNC16(kb + off,            g_Kh + g);
            CP_ASYNC16(kb + AMAT * 2 + off, g_Kl + g);
        }
    };
    auto load_v = [&](int n0) {
        for (int i = tid; i < 512; i += 128) {
            int row = i >> 3, q = i & 7;
            uint32_t off = (uint32_t)(row * AST + q * 8) * 2;
            size_t g = (rowbase + n0 + row) * (size_t)DM + colb + q * 8;
            CP_ASYNC16(vbase + off,            g_Vh + g);
            CP_ASYNC16(vbase + AMAT * 2 + off, g_Vl + g);
        }
    };

    load_k(0, 0);
    CP_COMMIT();

    const int T = m0 / 64 + 1;
    float l_i[2] = {0.f, 0.f};
    float O[8][4];
#pragma unroll
    for (int j = 0; j < 8; j++)
#pragma unroll
        for (int t = 0; t < 4; t++) O[j][t] = 0.f;

    uint32_t qh[4][4], ql[4][4];    // both Q hi and lo resident

    const int a_r = lane & 15;
    const int a_k = (lane >> 4) * 8;
    const int b_j = (lane >> 4) & 1;
    const int b_h = (lane >> 3) & 1;
    const int b_r = lane & 7;

    for (int t = 0; t < T; t++) {
        const int ks = t & 1;
        const uint32_t kbase = smb + (uint32_t)(2 + ks * 2) * AMAT * 2;

        __syncthreads();
        load_v(t * 64);
        CP_COMMIT();                     // pending: {K(t), V(t)} (+Q at t=0)
        CP_WAIT(1);                      // K(t) [and Q] complete
        __syncthreads();

        if (t == 0) {
#pragma unroll
            for (int kc = 0; kc < 4; kc++) {
                uint32_t ad = smb + (uint32_t)((wm + a_r) * AST + kc * 16 + a_k) * 2;
                ldsm_x4(qh[kc][0], qh[kc][1], qh[kc][2], qh[kc][3], ad);
                ldsm_x4(ql[kc][0], ql[kc][1], ql[kc][2], ql[kc][3], ad + AMAT * 2);
            }
        }

        // ---- QK^T on K(t) while V(t) streams in ----
        float sacc[8][4];
#pragma unroll
        for (int j = 0; j < 8; j++)
#pragma unroll
            for (int c = 0; c < 4; c++) sacc[j][c] = 0.f;

#pragma unroll
        for (int kc = 0; kc < 4; kc++) {
#pragma unroll
            for (int jp = 0; jp < 4; jp++) {
                uint32_t ad = kbase
                    + (uint32_t)(((jp * 2 + b_j) * 8 + b_r) * AST + kc * 16 + b_h * 8) * 2;
                uint32_t kh0, kh1, kh2, kh3, kl0, kl1, kl2, kl3;
                ldsm_x4(kh0, kh1, kh2, kh3, ad);
                ldsm_x4(kl0, kl1, kl2, kl3, ad + AMAT * 2);
                mma_bf16(sacc[jp*2],   qh[kc], kh0, kh1);
                mma_bf16(sacc[jp*2],   qh[kc], kl0, kl1);
                mma_bf16(sacc[jp*2],   ql[kc], kh0, kh1);
                mma_bf16(sacc[jp*2+1], qh[kc], kh2, kh3);
                mma_bf16(sacc[jp*2+1], qh[kc], kl2, kl3);
                mma_bf16(sacc[jp*2+1], ql[kc], kh2, kh3);
            }
        }

        // prefetch K(t+1) while we do exp + PV
        if (t + 1 < T) {
            load_k(ks ^ 1, (t + 1) * 64);
            CP_COMMIT();                 // pending: {V(t), K(t+1)}
            CP_WAIT(1);                  // V(t) complete
        } else {
            CP_WAIT(0);
        }
        __syncthreads();                 // V(t) visible to all warps

        // causal mask on diagonal tile
        if (t == T - 1) {
            const int qr0 = m0 + wm + r;
#pragma unroll
            for (int j = 0; j < 8; j++) {
                const int key0 = t * 64 + j * 8 + cq;
                if (key0 + 0 > qr0)     sacc[j][0] = -INFINITY;
                if (key0 + 1 > qr0)     sacc[j][1] = -INFINITY;
                if (key0 + 0 > qr0 + 8) sacc[j][2] = -INFINITY;
                if (key0 + 1 > qr0 + 8) sacc[j][3] = -INFINITY;
            }
        }

        // no-max softmax: p = 2^(s * EXPC)
#pragma unroll
        for (int j = 0; j < 8; j++) {
            sacc[j][0] = exp2f(sacc[j][0] * EXPC); l_i[0] += sacc[j][0];
            sacc[j][1] = exp2f(sacc[j][1] * EXPC); l_i[0] += sacc[j][1];
            sacc[j][2] = exp2f(sacc[j][2] * EXPC); l_i[1] += sacc[j][2];
            sacc[j][3] = exp2f(sacc[j][3] * EXPC); l_i[1] += sacc[j][3];
        }

        // ---- PV on V(t) while K(t+1) streams in ----
#pragma unroll
        for (int kc = 0; kc < 4; kc++) {
            uint32_t ph[4], pl[4];
#pragma unroll
            for (int half = 0; half < 2; half++) {
                const int jj = kc * 2 + half;
                split_pack(sacc[jj][0], sacc[jj][1], ph[half * 2 + 0], pl[half * 2 + 0]);
                split_pack(sacc[jj][2], sacc[jj][3], ph[half * 2 + 1], pl[half * 2 + 1]);
            }
            const int lrow = kc * 16 + (lane & 7) + ((lane >> 3) & 1) * 8;
            const int lcolh = (lane >> 4);
#pragma unroll
            for (int jp = 0; jp < 4; jp++) {
                uint32_t addr = vbase
                    + (uint32_t)(lrow * AST + (jp * 2 + lcolh) * 8) * 2;
                uint32_t vh0, vh1, vh2, vh3, vl0, vl1, vl2, vl3;
                ldsm_x4_trans(vh0, vh1, vh2, vh3, addr);
                ldsm_x4_trans(vl0, vl1, vl2, vl3, addr + AMAT * 2);
                mma_bf16(O[jp * 2],     ph, vh0, vh1);
                mma_bf16(O[jp * 2],     ph, vl0, vl1);
                mma_bf16(O[jp * 2],     pl, vh0, vh1);
                mma_bf16(O[jp * 2 + 1], ph, vh2, vh3);
                mma_bf16(O[jp * 2 + 1], ph, vl2, vl3);
                mma_bf16(O[jp * 2 + 1], pl, vh2, vh3);
            }
        }
    }

    // final l reduction across the quad
    l_i[0] += __shfl_xor_sync(0xffffffffu, l_i[0], 1);
    l_i[0] += __shfl_xor_sync(0xffffffffu, l_i[0], 2);
    l_i[1] += __shfl_xor_sync(0xffffffffu, l_i[1], 1);
    l_i[1] += __shfl_xor_sync(0xffffffffu, l_i[1], 2);
    const float inv0 = 1.f / l_i[0];
    const float inv1 = 1.f / l_i[1];
#pragma unroll
    for (int j = 0; j < 8; j++) {
        const int col = colb + j * 8 + cq;
        const size_t row0 = (rowbase + m0 + wm + r) * (size_t)DM + col;
        const size_t row8 = row0 + 8 * (size_t)DM;
        uint32_t ph0, pl0, ph1, pl1;
        split_pack(O[j][0] * inv0, O[j][1] * inv0, ph0, pl0);
        split_pack(O[j][2] * inv1, O[j][3] * inv1, ph1, pl1);
        *(uint32_t*)(g_Ahi + row0) = ph0;
        *(uint32_t*)(g_Ahi + row8) = ph1;
        *(uint32_t*)(g_Alo + row0) = pl0;
        *(uint32_t*)(g_Alo + row8) = pl1;
    }
}

// ================= launch =================
extern "C" void kernel_launch(void* const* d_in, const int* in_sizes, int n_in,
                              void* d_out, int out_size) {
    (void)in_sizes; (void)n_in; (void)out_size;
    const float* X  = (const float*)d_in[0];
    const float* Wq = (const float*)d_in[1];
    const float* Wk = (const float*)d_in[2];
    const float* Wv = (const float*)d_in[3];
    const float* Wo = (const float*)d_in[4];

    bf16 *xhi, *xlo;
    cudaGetSymbolAddress((void**)&xhi, g_Xhi);
    cudaGetSymbolAddress((void**)&xlo, g_Xlo);

    cudaFuncSetAttribute(gemm_qkv,
                         cudaFuncAttributeMaxDynamicSharedMemorySize, GEMM_SMEM_BYTES);
    cudaFuncSetAttribute(gemm_out,
                         cudaFuncAttributeMaxDynamicSharedMemorySize, GEMM_SMEM_BYTES);
    cudaFuncSetAttribute(attn_hmma,
                         cudaFuncAttributeMaxDynamicSharedMemorySize, ATT_SMEM_BYTES);

    {
        int n4 = MROWS * DM / 4;
        convert_hilo<<<(n4 + 255) / 256, 256>>>((const float4*)X, (uint2*)xhi, (uint2*)xlo, n4);
    }
    wtrans_all<<<dim3(DM / 32, DM / 32, 4), dim3(32, 8)>>>(Wq, Wk, Wv, Wo);

    gemm_qkv<<<dim3(DM / 128, MROWS / 128, 3), 128, GEMM_SMEM_BYTES>>>();

    attn_hmma<<<dim3(SEQ / 64, BATCH * NH), 128, ATT_SMEM_BYTES>>>();

    gemm_out<<<dim3(DM / 128, MROWS / 128), 128, GEMM_SMEM_BYTES>>>((float*)d_out);
}